// round 1
// baseline (speedup 1.0000x reference)
#include <cuda_runtime.h>
#include <cstddef>

// ---------------------------------------------------------------------------
// NCEAverageMultiview on GB300 — fully fused, HBM-bound implementation.
//
// Output layout in d_out (fp32):
//   [0,              B*KP1)        out_v1
//   [B*KP1,          2*B*KP1)      out_v2
//   [2*B*KP1,        2*B*KP1+N*D)  new_memory_v1
//   [2*B*KP1+N*D,    ...   )       new_memory_v2
// ---------------------------------------------------------------------------

__device__ double g_sum[2];   // sums of unnormalized exp values (out_v1, out_v2)

__global__ void init_sums_kernel() {
    g_sum[0] = 0.0;
    g_sum[1] = 0.0;
}

// One warp handles one (b, k) row: gathers 512B rows from both memory banks,
// dots against v1[b]/v2[b] held in registers, exp, writes unnormalized value,
// accumulates double partial sums.
__global__ void __launch_bounds__(256) dot_exp_kernel(
    const float* __restrict__ v1, const float* __restrict__ v2,
    const float* __restrict__ m1, const float* __restrict__ m2,
    const int* __restrict__ y, const int* __restrict__ idx,
    float* __restrict__ out1, float* __restrict__ out2,
    int KP1)
{
    const int b    = blockIdx.y;
    const int lane = threadIdx.x & 31;
    const int warp = threadIdx.x >> 5;
    const float invT = 1.0f / 0.07f;

    // v vectors for this b: 128 floats = one float4 per lane
    const float4 a1 = reinterpret_cast<const float4*>(v1 + (size_t)b * 128)[lane];
    const float4 a2 = reinterpret_cast<const float4*>(v2 + (size_t)b * 128)[lane];

    const int warpsPerB = gridDim.x * (blockDim.x >> 5);
    const int gw = blockIdx.x * (blockDim.x >> 5) + warp;
    const int yb = y[b];

    double acc1 = 0.0, acc2 = 0.0;

    for (int k = gw; k < KP1; k += warpsPerB) {
        const int i = (k == 0) ? yb : idx[(size_t)b * KP1 + k];
        const float4 x1 = reinterpret_cast<const float4*>(m1 + (size_t)i * 128)[lane];
        const float4 x2 = reinterpret_cast<const float4*>(m2 + (size_t)i * 128)[lane];

        // out_v1 = exp(<memory_v2[i], v1>/T);  out_v2 = exp(<memory_v1[i], v2>/T)
        float s1 = x2.x * a1.x + x2.y * a1.y + x2.z * a1.z + x2.w * a1.w;
        float s2 = x1.x * a2.x + x1.y * a2.y + x1.z * a2.z + x1.w * a2.w;

        #pragma unroll
        for (int o = 16; o; o >>= 1) {
            s1 += __shfl_xor_sync(0xffffffffu, s1, o);
            s2 += __shfl_xor_sync(0xffffffffu, s2, o);
        }

        if (lane == 0) {
            const float e1 = __expf(s1 * invT);
            const float e2 = __expf(s2 * invT);
            out1[(size_t)b * KP1 + k] = e1;
            out2[(size_t)b * KP1 + k] = e2;
            acc1 += (double)e1;
            acc2 += (double)e2;
        }
    }

    if (lane == 0) {
        atomicAdd(&g_sum[0], acc1);
        atomicAdd(&g_sum[1], acc2);
    }
}

// Scale out arrays in place by 1/Z = cnt / (sum * N)
__global__ void normalize_kernel(float* __restrict__ out1, float* __restrict__ out2,
                                 int total, double nOutput)
{
    const double cnt = (double)total;
    const float f1 = (float)(cnt / (g_sum[0] * nOutput));
    const float f2 = (float)(cnt / (g_sum[1] * nOutput));
    const int i = blockIdx.x * blockDim.x + threadIdx.x;
    if (i < total) {
        out1[i] *= f1;
        out2[i] *= f2;
    }
}

// Bulk float4 copy (grid-stride)
__global__ void __launch_bounds__(256) copy_kernel(float4* __restrict__ dst,
                                                   const float4* __restrict__ src,
                                                   size_t n4)
{
    size_t i = (size_t)blockIdx.x * blockDim.x + threadIdx.x;
    const size_t stride = (size_t)gridDim.x * blockDim.x;
    for (; i < n4; i += stride) dst[i] = src[i];
}

// Momentum scatter update: pos = 0.5*mem[y[b]] + 0.5*v[b], L2-normalized.
// Last-duplicate-wins: block b skips if a later b' has the same y.
__global__ void update_kernel(
    const float* __restrict__ v1, const float* __restrict__ v2,
    const float* __restrict__ m1, const float* __restrict__ m2,
    const int* __restrict__ y,
    float* __restrict__ om1, float* __restrict__ om2,
    int B)
{
    const int b    = blockIdx.x;
    const int lane = threadIdx.x;   // 32 threads
    const int yb   = y[b];

    for (int b2 = b + 1; b2 < B; ++b2)
        if (y[b2] == yb) return;    // a later duplicate will write this row

    // memory_v1 update uses v1, memory_v2 uses v2
    {
        const float4 mv = reinterpret_cast<const float4*>(m1 + (size_t)yb * 128)[lane];
        const float4 vv = reinterpret_cast<const float4*>(v1 + (size_t)b  * 128)[lane];
        float4 p;
        p.x = 0.5f * (mv.x + vv.x);
        p.y = 0.5f * (mv.y + vv.y);
        p.z = 0.5f * (mv.z + vv.z);
        p.w = 0.5f * (mv.w + vv.w);
        float ss = p.x * p.x + p.y * p.y + p.z * p.z + p.w * p.w;
        #pragma unroll
        for (int o = 16; o; o >>= 1) ss += __shfl_xor_sync(0xffffffffu, ss, o);
        const float inv = 1.0f / sqrtf(ss);
        p.x *= inv; p.y *= inv; p.z *= inv; p.w *= inv;
        reinterpret_cast<float4*>(om1 + (size_t)yb * 128)[lane] = p;
    }
    {
        const float4 mv = reinterpret_cast<const float4*>(m2 + (size_t)yb * 128)[lane];
        const float4 vv = reinterpret_cast<const float4*>(v2 + (size_t)b  * 128)[lane];
        float4 p;
        p.x = 0.5f * (mv.x + vv.x);
        p.y = 0.5f * (mv.y + vv.y);
        p.z = 0.5f * (mv.z + vv.z);
        p.w = 0.5f * (mv.w + vv.w);
        float ss = p.x * p.x + p.y * p.y + p.z * p.z + p.w * p.w;
        #pragma unroll
        for (int o = 16; o; o >>= 1) ss += __shfl_xor_sync(0xffffffffu, ss, o);
        const float inv = 1.0f / sqrtf(ss);
        p.x *= inv; p.y *= inv; p.z *= inv; p.w *= inv;
        reinterpret_cast<float4*>(om2 + (size_t)yb * 128)[lane] = p;
    }
}

extern "C" void kernel_launch(void* const* d_in, const int* in_sizes, int n_in,
                              void* d_out, int out_size)
{
    const float* v1  = (const float*)d_in[0];
    const float* v2  = (const float*)d_in[1];
    const float* m1  = (const float*)d_in[2];
    const float* m2  = (const float*)d_in[3];
    const int*   y   = (const int*)d_in[4];
    const int*   idx = (const int*)d_in[5];

    const int B = in_sizes[4];                 // 256
    const int D = in_sizes[0] / B;             // 128
    const size_t ND = (size_t)in_sizes[2];     // N*D = 128M
    const int KP1 = in_sizes[5] / B;           // 4097
    const int Nout = (int)(ND / (size_t)D);    // 1,000,000

    float* out  = (float*)d_out;
    float* out1 = out;
    float* out2 = out + (size_t)B * KP1;
    float* om1  = out + 2 * (size_t)B * KP1;
    float* om2  = om1 + ND;

    // 1) zero accumulators
    init_sums_kernel<<<1, 1>>>();

    // 2) gather + dot + exp + partial sums
    dim3 grid(16, B);
    dot_exp_kernel<<<grid, 256>>>(v1, v2, m1, m2, y, idx, out1, out2, KP1);

    // 3) normalize in place
    const int total = B * KP1;
    normalize_kernel<<<(total + 255) / 256, 256>>>(out1, out2, total, (double)Nout);

    // 4) bulk copies of memory banks
    const size_t n4 = ND / 4;
    copy_kernel<<<2368, 256>>>((float4*)om1, (const float4*)m1, n4);
    copy_kernel<<<2368, 256>>>((float4*)om2, (const float4*)m2, n4);

    // 5) momentum scatter update (overwrites B rows in the copies)
    update_kernel<<<B, 32>>>(v1, v2, m1, m2, y, om1, om2, B);
}